// round 8
// baseline (speedup 1.0000x reference)
#include <cuda_runtime.h>
#include <cuda_fp16.h>
#include <cstdint>

// DAS beamform, round 8: fp16 staging + TMA bulk fills.
//   Kernel 1: convert rf f32 -> fp16 into __device__ scratch (8MB -> 4MB).
//   Kernel 2: ring of 3 x 32KB pair-buffers filled by ONE cp.async.bulk per
//             2 channels (issued by tid0, mbarrier complete_tx), gathers via
//             LDS.64, lerp + accumulate in f32. One bar.sync per iteration.

#define NC      128
#define NS      2048
#define NPIX    65536
#define THREADS 1024
#define PX_PER_BLOCK 886
#define TILES_PER_BATCH 74
#define GRID    (2 * TILES_PER_BATCH)   // 148

#define CH_BYTES   (NS * 8)             // 16 KB per channel (fp16, K=4)
#define PAIR_BYTES (2 * CH_BYTES)       // 32 KB: channels c, c+1 contiguous
#define PAIR_FLOATS (PAIR_BYTES / 4)
#define SPR_OFF_B  (3 * PAIR_BYTES)             // 98304
#define MBAR_OFF_B (SPR_OFF_B + NC * 3 * 4)     // 99840 (8-aligned)
#define SMEM_BYTES (MBAR_OFF_B + 3 * 8)

// fp16 copy of rf: [B, Nc, Ns, K] halves = 4 MB (module scratch, allowed)
__device__ __align__(16) __half RF16[2 * NC * NS * 4];

__global__ __launch_bounds__(256)
void conv_kernel(const float4* __restrict__ rf4)
{
    const int idx = blockIdx.x * blockDim.x + threadIdx.x;   // 0 .. 262143
    const float4 a = rf4[2 * idx];
    const float4 b = rf4[2 * idx + 1];
    __half2 h0 = __float22half2_rn(make_float2(a.x, a.y));
    __half2 h1 = __float22half2_rn(make_float2(a.z, a.w));
    __half2 h2 = __float22half2_rn(make_float2(b.x, b.y));
    __half2 h3 = __float22half2_rn(make_float2(b.z, b.w));
    uint4 o;
    o.x = *reinterpret_cast<uint32_t*>(&h0);
    o.y = *reinterpret_cast<uint32_t*>(&h1);
    o.z = *reinterpret_cast<uint32_t*>(&h2);
    o.w = *reinterpret_cast<uint32_t*>(&h3);
    reinterpret_cast<uint4*>(RF16)[idx] = o;
}

__device__ __forceinline__ uint32_t smem_u32(const void* p) {
    uint32_t a;
    asm("{ .reg .u64 t; cvta.to.shared.u64 t, %1; cvt.u32.u64 %0, t; }"
        : "=r"(a) : "l"(p));
    return a;
}

__device__ __forceinline__ void mbar_init(uint32_t mbar, uint32_t count) {
    asm volatile("mbarrier.init.shared.b64 [%0], %1;" :: "r"(mbar), "r"(count) : "memory");
}

__device__ __forceinline__ void mbar_expect_tx(uint32_t mbar, uint32_t bytes) {
    asm volatile("mbarrier.arrive.expect_tx.shared.b64 _, [%0], %1;"
                 :: "r"(mbar), "r"(bytes) : "memory");
}

__device__ __forceinline__ void bulk_g2s(uint32_t dst, const void* src,
                                         uint32_t bytes, uint32_t mbar) {
    asm volatile(
        "cp.async.bulk.shared::cta.global.mbarrier::complete_tx::bytes "
        "[%0], [%1], %2, [%3];"
        :: "r"(dst), "l"(src), "r"(bytes), "r"(mbar) : "memory");
}

__device__ __forceinline__ void mbar_wait(uint32_t mbar, uint32_t parity) {
    uint32_t done;
    asm volatile(
        "{\n\t"
        ".reg .pred p;\n\t"
        "mbarrier.try_wait.parity.acquire.cta.shared::cta.b64 p, [%1], %2;\n\t"
        "selp.b32 %0, 1, 0, p;\n\t"
        "}"
        : "=r"(done) : "r"(mbar), "r"(parity) : "memory");
    if (!done) {
        asm volatile(
            "{\n\t"
            ".reg .pred P1;\n\t"
            "WAIT_LOOP_%=:\n\t"
            "mbarrier.try_wait.parity.acquire.cta.shared::cta.b64 P1, [%0], %1, 0x989680;\n\t"
            "@P1 bra.uni WAIT_DONE_%=;\n\t"
            "bra.uni WAIT_LOOP_%=;\n\t"
            "WAIT_DONE_%=:\n\t"
            "}"
            :: "r"(mbar), "r"(parity) : "memory");
    }
}

__global__ __launch_bounds__(THREADS, 1)
void das_kernel(const float* __restrict__ g,
                const float* __restrict__ pr,
                const float* __restrict__ p,
                float* __restrict__ out)
{
    extern __shared__ float smem[];
    float* spr = smem + SPR_OFF_B / 4;

    const int tid  = threadIdx.x;
    const int b    = blockIdx.x / TILES_PER_BATCH;
    const int tile = blockIdx.x % TILES_PER_BATCH;
    const int pix0 = tile * PX_PER_BLOCK + tid;
    const bool active = (tid < PX_PER_BLOCK) && (pix0 < NPIX);
    const int pix  = active ? pix0 : 0;

    const uint32_t smem_base = smem_u32(smem);
    const uint32_t mbar_base = smem_base + MBAR_OFF_B;

    if (tid == 0) {
        mbar_init(mbar_base + 0, 1);
        mbar_init(mbar_base + 8, 1);
        mbar_init(mbar_base + 16, 1);
    }
    if (tid < NC * 3) spr[tid] = pr[b * NC * 3 + tid];

    const float c0 = p[b * 4 + 0];
    const float fs = p[b * 4 + 1];
    const float t0 = p[b * 4 + 2];
    const float scale = fs / c0;
    const float gx = g[((size_t)b * NPIX + pix) * 3 + 0];
    const float gy = g[((size_t)b * NPIX + pix) * 3 + 1];
    const float gz = g[((size_t)b * NPIX + pix) * 3 + 2];
    const float sbase = scale * (t0 + gz);

    // fp16 source: per-batch base; channel c row = 16 KB
    const char* rf_base = reinterpret_cast<const char*>(RF16) + (size_t)b * NC * CH_BYTES;

    __syncthreads();   // mbar init + spr visible before any bulk completes / reads

    if (tid == 0) {
        // prologue: pairs 0 (ch 0,1) and 1 (ch 2,3)
        mbar_expect_tx(mbar_base + 0, PAIR_BYTES);
        bulk_g2s(smem_base + 0 * PAIR_BYTES, rf_base + 0 * CH_BYTES, PAIR_BYTES, mbar_base + 0);
        mbar_expect_tx(mbar_base + 8, PAIR_BYTES);
        bulk_g2s(smem_base + 1 * PAIR_BYTES, rf_base + 2 * CH_BYTES, PAIR_BYTES, mbar_base + 8);
    }

    float4 accA = make_float4(0.f, 0.f, 0.f, 0.f);
    float4 accB = make_float4(0.f, 0.f, 0.f, 0.f);

    #pragma unroll 1
    for (int t = 0; t < NC / 2; t++) {
        const int c = 2 * t;
        const int q = t / 3;
        const int pp = t - 3 * q;            // t % 3: ring pair index
        const uint32_t parity = (uint32_t)(q & 1);

        mbar_wait(mbar_base + pp * 8, parity);   // pair data ready (acquire)

        const float paxx = spr[c * 3 + 0], paxy = spr[c * 3 + 1], paxz = spr[c * 3 + 2];
        const float pbxx = spr[c * 3 + 3], pbxy = spr[c * 3 + 4], pbxz = spr[c * 3 + 5];

        float dax = gx - paxx, day = gy - paxy, daz = gz - paxz;
        float dda = fmaf(dax, dax, fmaf(day, day, daz * daz));
        float da; asm("sqrt.approx.f32 %0, %1;" : "=f"(da) : "f"(dda));
        float sa = fmaf(scale, da, sbase);
        sa = fminf(fmaxf(sa, 0.0f), 2047.0f);
        int ia = min((int)sa, NS - 2);
        const float wa = sa - (float)ia, wa0 = 1.0f - wa;

        float dbx = gx - pbxx, dby = gy - pbxy, dbz = gz - pbxz;
        float ddb = fmaf(dbx, dbx, fmaf(dby, dby, dbz * dbz));
        float db; asm("sqrt.approx.f32 %0, %1;" : "=f"(db) : "f"(ddb));
        float sb = fmaf(scale, db, sbase);
        sb = fminf(fmaxf(sb, 0.0f), 2047.0f);
        int ib = min((int)sb, NS - 2);
        const float wb = sb - (float)ib, wb0 = 1.0f - wb;

        const char* pair_ptr = reinterpret_cast<const char*>(smem) + pp * PAIR_BYTES;
        const uint2* bufA = reinterpret_cast<const uint2*>(pair_ptr);
        const uint2* bufB = reinterpret_cast<const uint2*>(pair_ptr + CH_BYTES);

        if (active) {
            uint2 ra0 = bufA[ia];
            uint2 ra1 = bufA[ia + 1];
            uint2 rb0 = bufB[ib];
            uint2 rb1 = bufB[ib + 1];

            float2 a0lo = __half22float2(*reinterpret_cast<__half2*>(&ra0.x));
            float2 a0hi = __half22float2(*reinterpret_cast<__half2*>(&ra0.y));
            float2 a1lo = __half22float2(*reinterpret_cast<__half2*>(&ra1.x));
            float2 a1hi = __half22float2(*reinterpret_cast<__half2*>(&ra1.y));

            accA.x = fmaf(wa0, a0lo.x, fmaf(wa, a1lo.x, accA.x));
            accA.y = fmaf(wa0, a0lo.y, fmaf(wa, a1lo.y, accA.y));
            accA.z = fmaf(wa0, a0hi.x, fmaf(wa, a1hi.x, accA.z));
            accA.w = fmaf(wa0, a0hi.y, fmaf(wa, a1hi.y, accA.w));

            float2 b0lo = __half22float2(*reinterpret_cast<__half2*>(&rb0.x));
            float2 b0hi = __half22float2(*reinterpret_cast<__half2*>(&rb0.y));
            float2 b1lo = __half22float2(*reinterpret_cast<__half2*>(&rb1.x));
            float2 b1hi = __half22float2(*reinterpret_cast<__half2*>(&rb1.y));

            accB.x = fmaf(wb0, b0lo.x, fmaf(wb, b1lo.x, accB.x));
            accB.y = fmaf(wb0, b0lo.y, fmaf(wb, b1lo.y, accB.y));
            accB.z = fmaf(wb0, b0hi.x, fmaf(wb, b1hi.x, accB.z));
            accB.w = fmaf(wb0, b0hi.y, fmaf(wb, b1hi.y, accB.w));
        }

        // all threads finished reading ring slot (pp+2)%3 (read at iter t-1 and
        // earlier) before tid0 overwrites it with channels c+4, c+5.
        __syncthreads();
        if (c + 4 < NC && tid == 0) {
            int fp = pp + 2; if (fp >= 3) fp -= 3;
            mbar_expect_tx(mbar_base + fp * 8, PAIR_BYTES);
            bulk_g2s(smem_base + fp * PAIR_BYTES,
                     rf_base + (size_t)(c + 4) * CH_BYTES,
                     PAIR_BYTES, mbar_base + fp * 8);
        }
    }

    if (active) {
        float4 r;
        r.x = accA.x + accB.x;
        r.y = accA.y + accB.y;
        r.z = accA.z + accB.z;
        r.w = accA.w + accB.w;
        reinterpret_cast<float4*>(out)[(size_t)b * NPIX + pix0] = r;
    }
}

extern "C" void kernel_launch(void* const* d_in, const int* in_sizes, int n_in,
                              void* d_out, int out_size)
{
    const float* rf = (const float*)d_in[0];
    const float* g  = (const float*)d_in[1];
    const float* pr = (const float*)d_in[2];
    const float* p  = (const float*)d_in[3];
    float* out = (float*)d_out;

    conv_kernel<<<1024, 256>>>(reinterpret_cast<const float4*>(rf));

    cudaFuncSetAttribute(das_kernel, cudaFuncAttributeMaxDynamicSharedMemorySize, SMEM_BYTES);
    das_kernel<<<GRID, THREADS, SMEM_BYTES>>>(g, pr, p, out);
}

// round 11
// speedup vs baseline: 1.2098x; 1.2098x over previous
#include <cuda_runtime.h>
#include <cuda_fp16.h>
#include <cstdint>

// DAS beamform, round 9: fp16 staging + TMA bulk group fills.
//   Ring of 3 x 64KB slots (4 channels each). One cp.async.bulk, one
//   mbar_wait, one bar.sync per 4 channels (32 iterations). Gathers LDS.64,
//   f32 lerp+accumulate (numerics identical to round 7/8).

#define NC      128
#define NS      2048
#define NPIX    65536
#define THREADS 1024
#define PX_PER_BLOCK 886
#define TILES_PER_BATCH 74
#define GRID    (2 * TILES_PER_BATCH)   // 148

#define CH_BYTES   (NS * 8)             // 16 KB per channel (fp16, K=4)
#define GRP_CH     4
#define GRP_BYTES  (GRP_CH * CH_BYTES)  // 64 KB per group
#define NGRP       (NC / GRP_CH)        // 32 iterations
#define SPR_OFF_B  (3 * GRP_BYTES)              // 196608
#define MBAR_OFF_B (SPR_OFF_B + NC * 16)        // 198656 (pr as float4)
#define SMEM_BYTES (MBAR_OFF_B + 3 * 8)

// fp16 copy of rf: [B, Nc, Ns, K] halves = 4 MB (module scratch, allowed)
__device__ __align__(16) __half RF16[2 * NC * NS * 4];

__global__ __launch_bounds__(256)
void conv_kernel(const float4* __restrict__ rf4)
{
    const int idx = blockIdx.x * blockDim.x + threadIdx.x;   // 0 .. 262143
    const float4 a = rf4[2 * idx];
    const float4 b = rf4[2 * idx + 1];
    __half2 h0 = __float22half2_rn(make_float2(a.x, a.y));
    __half2 h1 = __float22half2_rn(make_float2(a.z, a.w));
    __half2 h2 = __float22half2_rn(make_float2(b.x, b.y));
    __half2 h3 = __float22half2_rn(make_float2(b.z, b.w));
    uint4 o;
    o.x = *reinterpret_cast<uint32_t*>(&h0);
    o.y = *reinterpret_cast<uint32_t*>(&h1);
    o.z = *reinterpret_cast<uint32_t*>(&h2);
    o.w = *reinterpret_cast<uint32_t*>(&h3);
    reinterpret_cast<uint4*>(RF16)[idx] = o;
}

__device__ __forceinline__ uint32_t smem_u32(const void* p) {
    uint32_t a;
    asm("{ .reg .u64 t; cvta.to.shared.u64 t, %1; cvt.u32.u64 %0, t; }"
        : "=r"(a) : "l"(p));
    return a;
}

__device__ __forceinline__ void mbar_init(uint32_t mbar, uint32_t count) {
    asm volatile("mbarrier.init.shared.b64 [%0], %1;" :: "r"(mbar), "r"(count) : "memory");
}

__device__ __forceinline__ void mbar_expect_tx(uint32_t mbar, uint32_t bytes) {
    asm volatile("mbarrier.arrive.expect_tx.shared.b64 _, [%0], %1;"
                 :: "r"(mbar), "r"(bytes) : "memory");
}

__device__ __forceinline__ void bulk_g2s(uint32_t dst, const void* src,
                                         uint32_t bytes, uint32_t mbar) {
    asm volatile(
        "cp.async.bulk.shared::cta.global.mbarrier::complete_tx::bytes "
        "[%0], [%1], %2, [%3];"
        :: "r"(dst), "l"(src), "r"(bytes), "r"(mbar) : "memory");
}

__device__ __forceinline__ void mbar_wait(uint32_t mbar, uint32_t parity) {
    uint32_t done;
    asm volatile(
        "{\n\t"
        ".reg .pred p;\n\t"
        "mbarrier.try_wait.parity.acquire.cta.shared::cta.b64 p, [%1], %2;\n\t"
        "selp.b32 %0, 1, 0, p;\n\t"
        "}"
        : "=r"(done) : "r"(mbar), "r"(parity) : "memory");
    if (!done) {
        asm volatile(
            "{\n\t"
            ".reg .pred P1;\n\t"
            "WAIT_LOOP_%=:\n\t"
            "mbarrier.try_wait.parity.acquire.cta.shared::cta.b64 P1, [%0], %1, 0x989680;\n\t"
            "@P1 bra.uni WAIT_DONE_%=;\n\t"
            "bra.uni WAIT_LOOP_%=;\n\t"
            "WAIT_DONE_%=:\n\t"
            "}"
            :: "r"(mbar), "r"(parity) : "memory");
    }
}

__global__ __launch_bounds__(THREADS, 1)
void das_kernel(const float* __restrict__ g,
                const float* __restrict__ pr,
                const float* __restrict__ p,
                float* __restrict__ out)
{
    extern __shared__ char smem[];
    float4* spr4 = reinterpret_cast<float4*>(smem + SPR_OFF_B);

    const int tid  = threadIdx.x;
    const int b    = blockIdx.x / TILES_PER_BATCH;
    const int tile = blockIdx.x % TILES_PER_BATCH;
    const int pix0 = tile * PX_PER_BLOCK + tid;
    const bool active = (tid < PX_PER_BLOCK) && (pix0 < NPIX);
    const int pix  = active ? pix0 : 0;

    const uint32_t smem_base = smem_u32(smem);
    const uint32_t mbar_base = smem_base + MBAR_OFF_B;

    if (tid == 0) {
        mbar_init(mbar_base + 0, 1);
        mbar_init(mbar_base + 8, 1);
        mbar_init(mbar_base + 16, 1);
    }
    // pr cache as float4 (pad w=0): one LDS.128 broadcast per channel later
    if (tid < NC) {
        float4 v;
        v.x = pr[b * NC * 3 + tid * 3 + 0];
        v.y = pr[b * NC * 3 + tid * 3 + 1];
        v.z = pr[b * NC * 3 + tid * 3 + 2];
        v.w = 0.0f;
        spr4[tid] = v;
    }

    const float c0 = p[b * 4 + 0];
    const float fs = p[b * 4 + 1];
    const float t0 = p[b * 4 + 2];
    const float scale = fs / c0;
    const float gx = g[((size_t)b * NPIX + pix) * 3 + 0];
    const float gy = g[((size_t)b * NPIX + pix) * 3 + 1];
    const float gz = g[((size_t)b * NPIX + pix) * 3 + 2];
    const float sbase = scale * (t0 + gz);

    const char* rf_base = reinterpret_cast<const char*>(RF16) + (size_t)b * NC * CH_BYTES;

    __syncthreads();   // mbar init + spr visible

    if (tid == 0) {
        // prologue: groups 0 and 1 into slots 0 and 1
        mbar_expect_tx(mbar_base + 0, GRP_BYTES);
        bulk_g2s(smem_base + 0 * GRP_BYTES, rf_base + (size_t)0 * GRP_BYTES, GRP_BYTES, mbar_base + 0);
        mbar_expect_tx(mbar_base + 8, GRP_BYTES);
        bulk_g2s(smem_base + 1 * GRP_BYTES, rf_base + (size_t)1 * GRP_BYTES, GRP_BYTES, mbar_base + 8);
    }

    float4 acc0 = make_float4(0.f, 0.f, 0.f, 0.f);
    float4 acc1 = make_float4(0.f, 0.f, 0.f, 0.f);
    float4 acc2 = make_float4(0.f, 0.f, 0.f, 0.f);
    float4 acc3 = make_float4(0.f, 0.f, 0.f, 0.f);
    float4* accp[4] = { &acc0, &acc1, &acc2, &acc3 };

    int slot = 0;        // ring slot for this iteration
    int phase = 0;       // wait parity for this slot

    #pragma unroll 1
    for (int t = 0; t < NGRP; t++) {
        const int c = t * GRP_CH;

        if (active) {
            mbar_wait(mbar_base + slot * 8, (uint32_t)phase);

            const char* grp_ptr = smem + slot * GRP_BYTES;

            #pragma unroll
            for (int j = 0; j < GRP_CH; j++) {
                const float4 prc = spr4[c + j];      // LDS.128 broadcast

                const float dx = gx - prc.x;
                const float dy = gy - prc.y;
                const float dz = gz - prc.z;
                const float dd = fmaf(dx, dx, fmaf(dy, dy, dz * dz));
                float d; asm("sqrt.approx.f32 %0, %1;" : "=f"(d) : "f"(dd));
                float s = fmaf(scale, d, sbase);
                s = fminf(fmaxf(s, 0.0f), 2047.0f);
                int i0 = min((int)s, NS - 2);
                const float w  = s - (float)i0;
                const float w0 = 1.0f - w;

                const uint2* buf = reinterpret_cast<const uint2*>(grp_ptr + j * CH_BYTES);
                uint2 r0 = buf[i0];
                uint2 r1 = buf[i0 + 1];

                float2 y0lo = __half22float2(*reinterpret_cast<__half2*>(&r0.x));
                float2 y0hi = __half22float2(*reinterpret_cast<__half2*>(&r0.y));
                float2 y1lo = __half22float2(*reinterpret_cast<__half2*>(&r1.x));
                float2 y1hi = __half22float2(*reinterpret_cast<__half2*>(&r1.y));

                float4& a = *accp[j];
                a.x = fmaf(w0, y0lo.x, fmaf(w, y1lo.x, a.x));
                a.y = fmaf(w0, y0lo.y, fmaf(w, y1lo.y, a.y));
                a.z = fmaf(w0, y0hi.x, fmaf(w, y1hi.x, a.z));
                a.w = fmaf(w0, y0hi.y, fmaf(w, y1hi.y, a.w));
            }
        }

        // all reads of slot (slot+2)%3 (last used at iter t-1) complete before refill
        __syncthreads();
        if (t + 2 < NGRP && tid == 0) {
            int fslot = slot + 2; if (fslot >= 3) fslot -= 3;
            mbar_expect_tx(mbar_base + fslot * 8, GRP_BYTES);
            bulk_g2s(smem_base + fslot * GRP_BYTES,
                     rf_base + (size_t)(t + 2) * GRP_BYTES,
                     GRP_BYTES, mbar_base + fslot * 8);
        }

        if (++slot == 3) { slot = 0; phase ^= 1; }
    }

    if (active) {
        float4 r;
        r.x = (acc0.x + acc1.x) + (acc2.x + acc3.x);
        r.y = (acc0.y + acc1.y) + (acc2.y + acc3.y);
        r.z = (acc0.z + acc1.z) + (acc2.z + acc3.z);
        r.w = (acc0.w + acc1.w) + (acc2.w + acc3.w);
        reinterpret_cast<float4*>(out)[(size_t)b * NPIX + pix0] = r;
    }
}

extern "C" void kernel_launch(void* const* d_in, const int* in_sizes, int n_in,
                              void* d_out, int out_size)
{
    const float* rf = (const float*)d_in[0];
    const float* g  = (const float*)d_in[1];
    const float* pr = (const float*)d_in[2];
    const float* p  = (const float*)d_in[3];
    float* out = (float*)d_out;

    conv_kernel<<<1024, 256>>>(reinterpret_cast<const float4*>(rf));

    cudaFuncSetAttribute(das_kernel, cudaFuncAttributeMaxDynamicSharedMemorySize, SMEM_BYTES);
    das_kernel<<<GRID, THREADS, SMEM_BYTES>>>(g, pr, p, out);
}